// round 7
// baseline (speedup 1.0000x reference)
#include <cuda_runtime.h>
#include <cuda_fp16.h>
#include <cstdint>
#include <cstddef>

#define SCALE_F 0.125f

__device__ __forceinline__ uint32_t smem_to_u32(const void* p) {
    uint32_t a;
    asm("{ .reg .u64 t; cvta.to.shared.u64 t, %1; cvt.u32.u64 %0, t; }" : "=r"(a) : "l"(p));
    return a;
}
__device__ __forceinline__ void cp16(uint32_t dst, const void* src) {
    asm volatile("cp.async.cg.shared.global [%0], [%1], 16;" :: "r"(dst), "l"(src) : "memory");
}
#define CP_COMMIT() asm volatile("cp.async.commit_group;" ::: "memory")
template <int N>
__device__ __forceinline__ void cp_wait() {
    asm volatile("cp.async.wait_group %0;" :: "n"(N) : "memory");
}
__device__ __forceinline__ void ldm_x4(uint32_t& r0, uint32_t& r1, uint32_t& r2,
                                       uint32_t& r3, uint32_t addr) {
    asm volatile("ldmatrix.sync.aligned.m8n8.x4.shared.b16 {%0,%1,%2,%3}, [%4];"
                 : "=r"(r0), "=r"(r1), "=r"(r2), "=r"(r3) : "r"(addr));
}
__device__ __forceinline__ void ldm_x4t(uint32_t& r0, uint32_t& r1, uint32_t& r2,
                                        uint32_t& r3, uint32_t addr) {
    asm volatile("ldmatrix.sync.aligned.m8n8.x4.trans.shared.b16 {%0,%1,%2,%3}, [%4];"
                 : "=r"(r0), "=r"(r1), "=r"(r2), "=r"(r3) : "r"(addr));
}
__device__ __forceinline__ void mma_f16(float c[4], uint32_t a0, uint32_t a1,
                                        uint32_t a2, uint32_t a3, uint32_t b0,
                                        uint32_t b1) {
    asm volatile(
        "mma.sync.aligned.m16n8k16.row.col.f32.f16.f16.f32 "
        "{%0,%1,%2,%3},{%4,%5,%6,%7},{%8,%9},{%0,%1,%2,%3};\n"
        : "+f"(c[0]), "+f"(c[1]), "+f"(c[2]), "+f"(c[3])
        : "r"(a0), "r"(a1), "r"(a2), "r"(a3), "r"(b0), "r"(b1));
}
__device__ __forceinline__ uint32_t packh2(float lo, float hi) {
    __half2 h = __floats2half2_rn(lo, hi);
    return *(uint32_t*)&h;
}

// ===================== scratch =====================
__device__ __align__(16) __half g_x16[2 * 256 * 4096];     // [b][c][n]
__device__ __align__(16) __half g_w16[768 * 256];          // [o][c]
__device__ __align__(16) __half g_q16[2 * 4 * 4096 * 64];  // [bh][n][d], pre-scaled x0.125
__device__ __align__(16) __half g_k16[2 * 4 * 4096 * 64];  // [bh][n][d]
__device__ __align__(16) __half g_v16[2 * 4 * 64 * 4096];  // [bh][dv][m]
__device__ float g_qh[8 * 4096 * 128];                     // [bh][n][r]
__device__ float g_qw[8 * 4096 * 128];

// ---------------------------------------------------------------------------
// Kernel 0: fp32 -> fp16 conversion for x and w
// ---------------------------------------------------------------------------
#define X_F4 524288   // 2*256*4096 / 4
#define W_F4 49152    // 768*256 / 4
__global__ void __launch_bounds__(256) cvt_kernel(const float* __restrict__ x,
                                                  const float* __restrict__ w) {
    const int idx = blockIdx.x * 256 + threadIdx.x;
    if (idx < X_F4) {
        float4 v = ((const float4*)x)[idx];
        __half2* o = (__half2*)g_x16 + idx * 2;
        o[0] = __floats2half2_rn(v.x, v.y);
        o[1] = __floats2half2_rn(v.z, v.w);
    } else if (idx < X_F4 + W_F4) {
        float4 v = ((const float4*)w)[idx - X_F4];
        __half2* o = (__half2*)g_w16 + (idx - X_F4) * 2;
        o[0] = __floats2half2_rn(v.x, v.y);
        o[1] = __floats2half2_rn(v.z, v.w);
    }
}

// ---------------------------------------------------------------------------
// Kernel 1: QKV projection, fp16 tensor-core GEMM (unchanged from R6).
// ---------------------------------------------------------------------------
__global__ void __launch_bounds__(256, 1) qkv_mma_kernel() {
    extern __shared__ __align__(128) char smem[];
    const uint32_t sb = smem_to_u32(smem);
    const int t = threadIdx.x;
    const int w = t >> 5, lane = t & 31;
    const int gid = lane >> 2, tig = lane & 3;
    const int wo = w >> 1, wn = w & 1;
    const int n0 = blockIdx.x * 128;
    const int ot = blockIdx.y;
    const int b = blockIdx.z;

    const __half* wg = g_w16 + (size_t)ot * 128 * 256;
    const __half* xg = g_x16 + (size_t)b * 256 * 4096 + n0;

    auto load_stage = [&](int kc, int s) {
        const uint32_t As = sb + s * 32768;
        const uint32_t Bs = As + 16384;
        for (int idx = t; idx < 1024; idx += 256) {
            int row = idx >> 3, ch = idx & 7;
            cp16(As + row * 128 + ((ch ^ (row & 7)) * 16),
                 wg + (size_t)row * 256 + kc * 64 + ch * 8);
        }
        for (int idx = t; idx < 1024; idx += 256) {
            int row = idx >> 4, ch = idx & 15;
            cp16(Bs + row * 256 + ((ch ^ (row & 7)) * 16),
                 xg + (size_t)(kc * 64 + row) * 4096 + ch * 8);
        }
        CP_COMMIT();
    };

    float C[2][8][4];
#pragma unroll
    for (int mt = 0; mt < 2; mt++)
#pragma unroll
        for (int ng = 0; ng < 8; ng++)
#pragma unroll
            for (int e = 0; e < 4; e++) C[mt][ng][e] = 0.f;

    load_stage(0, 0);

    const int a_rlane = ((lane >> 3) & 1) * 8 + (lane & 7);
    const uint32_t a_x = (lane & 7) * 16;
    const int b_row = lane & 15;
    const int b_cg = lane >> 4;

    for (int kc = 0; kc < 4; kc++) {
        if (kc + 1 < 4) {
            load_stage(kc + 1, (kc + 1) & 1);
            cp_wait<1>();
        } else {
            cp_wait<0>();
        }
        __syncthreads();
        const uint32_t As = sb + (kc & 1) * 32768;
        const uint32_t Bs = As + 16384;

#pragma unroll
        for (int ks = 0; ks < 4; ks++) {
            uint32_t af[2][4];
#pragma unroll
            for (int mt = 0; mt < 2; mt++) {
                int arow = wo * 32 + mt * 16 + a_rlane;
                ldm_x4(af[mt][0], af[mt][1], af[mt][2], af[mt][3],
                       As + arow * 128 + (((uint32_t)((ks * 2 + (lane >> 4)) * 16)) ^ a_x));
            }
#pragma unroll
            for (int ng2 = 0; ng2 < 4; ng2++) {
                uint32_t b0, b1, b2, b3;
                int brow = ks * 16 + b_row;
                int bch = wn * 8 + ng2 * 2 + b_cg;
                ldm_x4t(b0, b1, b2, b3,
                        Bs + brow * 256 + ((bch ^ (brow & 7)) * 16));
#pragma unroll
                for (int mt = 0; mt < 2; mt++) {
                    mma_f16(C[mt][2 * ng2], af[mt][0], af[mt][1], af[mt][2], af[mt][3], b0, b1);
                    mma_f16(C[mt][2 * ng2 + 1], af[mt][0], af[mt][1], af[mt][2], af[mt][3], b2, b3);
                }
            }
        }
        __syncthreads();
    }

    const float sc = (ot < 2) ? SCALE_F : 1.0f;
    __half* Cs = (__half*)smem;
    if (ot < 4) {
#pragma unroll
        for (int mt = 0; mt < 2; mt++) {
            const int r_lo = wo * 32 + mt * 16 + gid, r_hi = r_lo + 8;
#pragma unroll
            for (int ng = 0; ng < 8; ng++) {
                const int c = wn * 64 + ng * 8 + 2 * tig;
                Cs[(c + 0) * 136 + r_lo] = __float2half_rn(C[mt][ng][0] * sc);
                Cs[(c + 1) * 136 + r_lo] = __float2half_rn(C[mt][ng][1] * sc);
                Cs[(c + 0) * 136 + r_hi] = __float2half_rn(C[mt][ng][2] * sc);
                Cs[(c + 1) * 136 + r_hi] = __float2half_rn(C[mt][ng][3] * sc);
            }
        }
        __syncthreads();
        __half* dst = (ot < 2) ? g_q16 : g_k16;
        const int otq = (ot < 2) ? ot : (ot - 2);
        for (int idx = t; idx < 2048; idx += 256) {
            int n = idx >> 4, hs = (idx >> 3) & 1, ch = idx & 7;
            int bh = b * 4 + otq * 2 + hs;
            *(uint4*)(dst + ((size_t)bh * 4096 + n0 + n) * 64 + ch * 8) =
                *(const uint4*)(Cs + n * 136 + hs * 64 + ch * 8);
        }
    } else {
#pragma unroll
        for (int mt = 0; mt < 2; mt++) {
            const int r_lo = wo * 32 + mt * 16 + gid, r_hi = r_lo + 8;
#pragma unroll
            for (int ng = 0; ng < 8; ng++) {
                const int c = wn * 64 + ng * 8 + 2 * tig;
                *(__half2*)(Cs + r_lo * 136 + c) = __floats2half2_rn(C[mt][ng][0], C[mt][ng][1]);
                *(__half2*)(Cs + r_hi * 136 + c) = __floats2half2_rn(C[mt][ng][2], C[mt][ng][3]);
            }
        }
        __syncthreads();
        const int otv = ot - 4;
        for (int idx = t; idx < 2048; idx += 256) {
            int lo = idx >> 4, ch = idx & 15;
            int bh = b * 4 + otv * 2 + (lo >> 6);
            int dv = lo & 63;
            *(uint4*)(g_v16 + ((size_t)bh * 64 + dv) * 4096 + n0 + ch * 8) =
                *(const uint4*)(Cs + lo * 136 + ch * 8);
        }
    }
}

// ---------------------------------------------------------------------------
// Kernel 2: rel-pos logits, fp16 mma (unchanged from R6).
// ---------------------------------------------------------------------------
__global__ void __launch_bounds__(256) rel_mma_kernel(const float* __restrict__ hrel,
                                                      const float* __restrict__ wrel) {
    __shared__ __align__(128) char smem_r[32768];
    const uint32_t sb = smem_to_u32(smem_r);
    const uint32_t Qs = sb;
    const uint32_t Rs = sb + 16384;
    const int t = threadIdx.x;
    const int w = t >> 5, lane = t & 31;
    const int gid = lane >> 2, tig = lane & 3;
    const int bh = blockIdx.y;
    const int n0 = blockIdx.x * 128;
    const float* rel = blockIdx.z ? wrel : hrel;
    float* outb = blockIdx.z ? g_qw : g_qh;

    for (int idx = t; idx < 1024; idx += 256) {
        int row = idx >> 3, ch = idx & 7;
        cp16(Qs + row * 128 + ((ch ^ (row & 7)) * 16),
             g_q16 + ((size_t)bh * 4096 + n0 + row) * 64 + ch * 8);
    }
    CP_COMMIT();
    for (int idx = t; idx < 1024; idx += 256) {
        int r = idx >> 3, ch = idx & 7;
        __half2 h[4];
        if (r < 127) {
            float4 v0 = *(const float4*)(rel + r * 64 + ch * 8);
            float4 v1 = *(const float4*)(rel + r * 64 + ch * 8 + 4);
            h[0] = __floats2half2_rn(v0.x * 8.f, v0.y * 8.f);
            h[1] = __floats2half2_rn(v0.z * 8.f, v0.w * 8.f);
            h[2] = __floats2half2_rn(v1.x * 8.f, v1.y * 8.f);
            h[3] = __floats2half2_rn(v1.z * 8.f, v1.w * 8.f);
        } else {
            h[0] = h[1] = h[2] = h[3] = __floats2half2_rn(0.f, 0.f);
        }
        *(uint4*)((char*)smem_r + 16384 + r * 128 + ((ch ^ (r & 7)) * 16)) = *(uint4*)h;
    }
    cp_wait<0>();
    __syncthreads();

    const int r0 = w * 16;
    uint32_t qf[4][4];
    {
        const int qrow = r0 + ((lane >> 3) & 1) * 8 + (lane & 7);
        const uint32_t qx = (lane & 7) * 16;
#pragma unroll
        for (int kt = 0; kt < 4; kt++)
            ldm_x4(qf[kt][0], qf[kt][1], qf[kt][2], qf[kt][3],
                   Qs + qrow * 128 + (((uint32_t)((kt * 2 + (lane >> 4)) * 16)) ^ qx));
    }

    const int kv_row = ((lane >> 4) & 1) * 8 + (lane & 7);
    const int kv_csel = (lane >> 3) & 1;
    const uint32_t kv_x = (lane & 7) * 16;

    float S[16][4];
#pragma unroll
    for (int nt = 0; nt < 16; nt++)
#pragma unroll
        for (int e = 0; e < 4; e++) S[nt][e] = 0.f;

#pragma unroll
    for (int kt = 0; kt < 4; kt++) {
#pragma unroll
        for (int ntp = 0; ntp < 8; ntp++) {
            uint32_t b0, b1, b2, b3;
            ldm_x4(b0, b1, b2, b3,
                   Rs + (uint32_t)(ntp * 16 + kv_row) * 128 +
                       (((uint32_t)((kt * 2 + kv_csel) * 16)) ^ kv_x));
            mma_f16(S[2 * ntp], qf[kt][0], qf[kt][1], qf[kt][2], qf[kt][3], b0, b1);
            mma_f16(S[2 * ntp + 1], qf[kt][0], qf[kt][1], qf[kt][2], qf[kt][3], b2, b3);
        }
    }

    const int i_lo = r0 + gid, i_hi = i_lo + 8;
#pragma unroll
    for (int nt = 0; nt < 16; nt++) {
        const int c = nt * 8 + 2 * tig;
        *(float2*)(outb + ((size_t)bh * 4096 + n0 + i_lo) * 128 + c) =
            make_float2(S[nt][0], S[nt][1]);
        *(float2*)(outb + ((size_t)bh * 4096 + n0 + i_hi) * 128 + c) =
            make_float2(S[nt][2], S[nt][3]);
    }
}

// ---------------------------------------------------------------------------
// Kernel 3: fp16 flash attention, 2 CTAs/SM. Width-bias tile in smem (Qw).
// ---------------------------------------------------------------------------
#define QW_STRIDE 66
#define QW_OFF 49152                                 // after Q + K/V buffers
#define FL_SMEM (49152 + 128 * QW_STRIDE * 4)        // 82944 B

__global__ void __launch_bounds__(256, 2) flash_kernel(float* __restrict__ out) {
    extern __shared__ __align__(128) char smem[];
    const uint32_t sb = smem_to_u32(smem);
    const uint32_t Qs = sb;  // 16384
    const uint32_t Kbuf0 = sb + 16384, Kbuf1 = sb + 24576;
    const uint32_t Vbuf0 = sb + 32768, Vbuf1 = sb + 40960;
    float* Qw = (float*)(smem + QW_OFF);  // [i][c] stride 66

    const int t = threadIdx.x;
    const int w = t >> 5, lane = t & 31;
    const int gid = lane >> 2, tig = lane & 3;
    const int r0 = w * 16;
    const int bh = blockIdx.y, qb = blockIdx.x;
    const int n0q = qb * 128;
    const __half* qg = g_q16 + (size_t)bh * 4096 * 64;
    const __half* kg = g_k16 + (size_t)bh * 4096 * 64;
    const __half* vg = g_v16 + (size_t)bh * 64 * 4096;

    for (int c = t; c < 1024; c += 256) {
        int row = c >> 3, kc = c & 7;
        cp16(Qs + row * 128 + ((kc * 16) ^ ((row & 7) * 16)),
             qg + (size_t)(n0q + row) * 64 + kc * 8);
    }
    for (int c = t; c < 512; c += 256) {
        int row = c >> 3, kc = c & 7;
        uint32_t sw = (kc * 16) ^ ((row & 7) * 16);
        cp16(Kbuf0 + row * 128 + sw, kg + (size_t)row * 64 + kc * 8);
        cp16(Vbuf0 + row * 128 + sw, vg + (size_t)row * 4096 + kc * 8);
    }
    CP_COMMIT();

    // ---- width-bias gather -> smem tile (each thread covers its own 16 cells)
    const int i_lo = r0 + gid, i_hi = i_lo + 8;
    {
        const float* qwb = g_qw + ((size_t)bh * 4096 + n0q) * 128;
#pragma unroll
        for (int nt = 0; nt < 8; nt++) {
            int c = nt * 8 + 2 * tig;
            Qw[i_lo * QW_STRIDE + c + 0] = qwb[(size_t)i_lo * 128 + (c - (i_lo & 63) + 63)];
            Qw[i_lo * QW_STRIDE + c + 1] = qwb[(size_t)i_lo * 128 + (c + 1 - (i_lo & 63) + 63)];
            Qw[i_hi * QW_STRIDE + c + 0] = qwb[(size_t)i_hi * 128 + (c - (i_hi & 63) + 63)];
            Qw[i_hi * QW_STRIDE + c + 1] = qwb[(size_t)i_hi * 128 + (c + 1 - (i_hi & 63) + 63)];
        }
    }
    cp_wait<0>();
    __syncthreads();

    uint32_t qf[4][4];
    {
        const int qrow = r0 + ((lane >> 3) & 1) * 8 + (lane & 7);
        const uint32_t qx = (lane & 7) * 16;
        const uint32_t qbase = Qs + qrow * 128;
#pragma unroll
        for (int kt = 0; kt < 4; kt++)
            ldm_x4(qf[kt][0], qf[kt][1], qf[kt][2], qf[kt][3],
                   qbase + ((uint32_t)((kt * 2 + (lane >> 4)) * 16) ^ qx));
    }

    const float* pqh_lo =
        g_qh + ((size_t)bh * 4096 + n0q + i_lo) * 128 + 63 - (qb * 2 + (i_lo >> 6));
    const float* pqh_hi =
        g_qh + ((size_t)bh * 4096 + n0q + i_hi) * 128 + 63 - (qb * 2 + (i_hi >> 6));
    const float* qw_lo = Qw + i_lo * QW_STRIDE + 2 * tig;
    const float* qw_hi = Qw + i_hi * QW_STRIDE + 2 * tig;

    const int kv_row = ((lane >> 4) & 1) * 8 + (lane & 7);
    const int kv_csel = (lane >> 3) & 1;
    const uint32_t kv_x = (lane & 7) * 16;

    float m_lo = -3.0e38f, m_hi = -3.0e38f, l_lo = 0.f, l_hi = 0.f;
    float O[8][4];
#pragma unroll
    for (int nt = 0; nt < 8; nt++)
#pragma unroll
        for (int e = 0; e < 4; e++) O[nt][e] = 0.f;

    for (int j = 0; j < 64; j++) {
        __syncthreads();
        if (j + 1 < 64) {
            const uint32_t kb = (j & 1) ? Kbuf0 : Kbuf1;
            const uint32_t vb = (j & 1) ? Vbuf0 : Vbuf1;
            for (int c = t; c < 512; c += 256) {
                int row = c >> 3, kc = c & 7;
                uint32_t sw = (kc * 16) ^ ((row & 7) * 16);
                cp16(kb + row * 128 + sw,
                     kg + ((size_t)(j + 1) * 64 + row) * 64 + kc * 8);
                cp16(vb + row * 128 + sw,
                     vg + (size_t)row * 4096 + (j + 1) * 64 + kc * 8);
            }
            CP_COMMIT();
            cp_wait<1>();
        } else {
            cp_wait<0>();
        }
        __syncthreads();

        const float qh_lo = pqh_lo[j], qh_hi = pqh_hi[j];
        const uint32_t Kb = (j & 1) ? Kbuf1 : Kbuf0;
        const uint32_t Vb = (j & 1) ? Vbuf1 : Vbuf0;

        float S[8][4];
#pragma unroll
        for (int nt = 0; nt < 8; nt++)
#pragma unroll
            for (int e = 0; e < 4; e++) S[nt][e] = 0.f;

#pragma unroll
        for (int kt = 0; kt < 4; kt++) {
#pragma unroll
            for (int ntp = 0; ntp < 4; ntp++) {
                uint32_t b0, b1, b2, b3;
                uint32_t addr = Kb + (uint32_t)(ntp * 16 + kv_row) * 128 +
                                ((uint32_t)((kt * 2 + kv_csel) * 16) ^ kv_x);
                ldm_x4(b0, b1, b2, b3, addr);
                mma_f16(S[2 * ntp], qf[kt][0], qf[kt][1], qf[kt][2], qf[kt][3], b0, b1);
                mma_f16(S[2 * ntp + 1], qf[kt][0], qf[kt][1], qf[kt][2], qf[kt][3], b2, b3);
            }
        }

        float mx_lo = -3.0e38f, mx_hi = -3.0e38f;
#pragma unroll
        for (int nt = 0; nt < 8; nt++) {
            const float2 b_lo = *(const float2*)(qw_lo + nt * 8);
            const float2 b_hi = *(const float2*)(qw_hi + nt * 8);
            S[nt][0] += qh_lo + b_lo.x;
            S[nt][1] += qh_lo + b_lo.y;
            S[nt][2] += qh_hi + b_hi.x;
            S[nt][3] += qh_hi + b_hi.y;
            mx_lo = fmaxf(mx_lo, fmaxf(S[nt][0], S[nt][1]));
            mx_hi = fmaxf(mx_hi, fmaxf(S[nt][2], S[nt][3]));
        }
        mx_lo = fmaxf(mx_lo, __shfl_xor_sync(0xffffffffu, mx_lo, 1));
        mx_lo = fmaxf(mx_lo, __shfl_xor_sync(0xffffffffu, mx_lo, 2));
        mx_hi = fmaxf(mx_hi, __shfl_xor_sync(0xffffffffu, mx_hi, 1));
        mx_hi = fmaxf(mx_hi, __shfl_xor_sync(0xffffffffu, mx_hi, 2));
        const float mnew_lo = fmaxf(m_lo, mx_lo);
        const float mnew_hi = fmaxf(m_hi, mx_hi);
        const float alpha_lo = __expf(m_lo - mnew_lo);
        const float alpha_hi = __expf(m_hi - mnew_hi);
        m_lo = mnew_lo; m_hi = mnew_hi;

        uint32_t ph[8][2];
        float sum_lo = 0.f, sum_hi = 0.f;
#pragma unroll
        for (int nt = 0; nt < 8; nt++) {
            float e0 = __expf(S[nt][0] - mnew_lo);
            float e1 = __expf(S[nt][1] - mnew_lo);
            float e2 = __expf(S[nt][2] - mnew_hi);
            float e3 = __expf(S[nt][3] - mnew_hi);
            sum_lo += e0 + e1;
            sum_hi += e2 + e3;
            ph[nt][0] = packh2(e0, e1);
            ph[nt][1] = packh2(e2, e3);
        }
        sum_lo += __shfl_xor_sync(0xffffffffu, sum_lo, 1);
        sum_lo += __shfl_xor_sync(0xffffffffu, sum_lo, 2);
        sum_hi += __shfl_xor_sync(0xffffffffu, sum_hi, 1);
        sum_hi += __shfl_xor_sync(0xffffffffu, sum_hi, 2);
        l_lo = l_lo * alpha_lo + sum_lo;
        l_hi = l_hi * alpha_hi + sum_hi;
#pragma unroll
        for (int nt = 0; nt < 8; nt++) {
            O[nt][0] *= alpha_lo; O[nt][1] *= alpha_lo;
            O[nt][2] *= alpha_hi; O[nt][3] *= alpha_hi;
        }

#pragma unroll
        for (int kt = 0; kt < 4; kt++) {
            const uint32_t pa0 = ph[2 * kt][0], pa1 = ph[2 * kt][1];
            const uint32_t pa2 = ph[2 * kt + 1][0], pa3 = ph[2 * kt + 1][1];
#pragma unroll
            for (int ntp = 0; ntp < 4; ntp++) {
                uint32_t b0, b1, b2, b3;
                uint32_t addr = Vb + (uint32_t)(ntp * 16 + kv_row) * 128 +
                                ((uint32_t)((kt * 2 + kv_csel) * 16) ^ kv_x);
                ldm_x4(b0, b1, b2, b3, addr);
                mma_f16(O[2 * ntp], pa0, pa1, pa2, pa3, b0, b1);
                mma_f16(O[2 * ntp + 1], pa0, pa1, pa2, pa3, b2, b3);
            }
        }
    }

    __syncthreads();
    const float inv_lo = 1.0f / l_lo, inv_hi = 1.0f / l_hi;
    float* Os = (float*)smem;
#pragma unroll
    for (int nt = 0; nt < 8; nt++) {
        int dv = nt * 8 + 2 * tig;
        Os[(dv + 0) * 132 + i_lo] = O[nt][0] * inv_lo;
        Os[(dv + 1) * 132 + i_lo] = O[nt][1] * inv_lo;
        Os[(dv + 0) * 132 + i_hi] = O[nt][2] * inv_hi;
        Os[(dv + 1) * 132 + i_hi] = O[nt][3] * inv_hi;
    }
    __syncthreads();

    const int b = bh >> 2, head = bh & 3;
    float* outp = out + ((size_t)(b * 256 + head * 64)) * 4096 + n0q;
    for (int idx = t * 4; idx < 8192; idx += 1024) {
        int dv = idx >> 7, i = idx & 127;
        *(float4*)(outp + (size_t)dv * 4096 + i) = *(const float4*)(Os + dv * 132 + i);
    }
}

// ---------------------------------------------------------------------------
extern "C" void kernel_launch(void* const* d_in, const int* in_sizes, int n_in,
                              void* d_out, int out_size) {
    const float* x = (const float*)d_in[0];
    const float* w = (const float*)d_in[1];
    const float* hrel = (const float*)d_in[2];
    const float* wrel = (const float*)d_in[3];
    float* out = (float*)d_out;

    cvt_kernel<<<(X_F4 + W_F4 + 255) / 256, 256>>>(x, w);

    cudaFuncSetAttribute(qkv_mma_kernel, cudaFuncAttributeMaxDynamicSharedMemorySize,
                         65536);
    qkv_mma_kernel<<<dim3(32, 6, 2), 256, 65536>>>();

    rel_mma_kernel<<<dim3(32, 8, 2), 256>>>(hrel, wrel);

    cudaFuncSetAttribute(flash_kernel, cudaFuncAttributeMaxDynamicSharedMemorySize,
                         FL_SMEM);
    flash_kernel<<<dim3(32, 8), 256, FL_SMEM>>>(out);
}

// round 8
// speedup vs baseline: 1.0865x; 1.0865x over previous
#include <cuda_runtime.h>
#include <cuda_fp16.h>
#include <cstdint>
#include <cstddef>

#define SCALE_F 0.125f

__device__ __forceinline__ uint32_t smem_to_u32(const void* p) {
    uint32_t a;
    asm("{ .reg .u64 t; cvta.to.shared.u64 t, %1; cvt.u32.u64 %0, t; }" : "=r"(a) : "l"(p));
    return a;
}
__device__ __forceinline__ void cp16(uint32_t dst, const void* src) {
    asm volatile("cp.async.cg.shared.global [%0], [%1], 16;" :: "r"(dst), "l"(src) : "memory");
}
#define CP_COMMIT() asm volatile("cp.async.commit_group;" ::: "memory")
template <int N>
__device__ __forceinline__ void cp_wait() {
    asm volatile("cp.async.wait_group %0;" :: "n"(N) : "memory");
}
__device__ __forceinline__ void ldm_x4(uint32_t& r0, uint32_t& r1, uint32_t& r2,
                                       uint32_t& r3, uint32_t addr) {
    asm volatile("ldmatrix.sync.aligned.m8n8.x4.shared.b16 {%0,%1,%2,%3}, [%4];"
                 : "=r"(r0), "=r"(r1), "=r"(r2), "=r"(r3) : "r"(addr));
}
__device__ __forceinline__ void ldm_x4t(uint32_t& r0, uint32_t& r1, uint32_t& r2,
                                        uint32_t& r3, uint32_t addr) {
    asm volatile("ldmatrix.sync.aligned.m8n8.x4.trans.shared.b16 {%0,%1,%2,%3}, [%4];"
                 : "=r"(r0), "=r"(r1), "=r"(r2), "=r"(r3) : "r"(addr));
}
__device__ __forceinline__ void mma_f16(float c[4], uint32_t a0, uint32_t a1,
                                        uint32_t a2, uint32_t a3, uint32_t b0,
                                        uint32_t b1) {
    asm volatile(
        "mma.sync.aligned.m16n8k16.row.col.f32.f16.f16.f32 "
        "{%0,%1,%2,%3},{%4,%5,%6,%7},{%8,%9},{%0,%1,%2,%3};\n"
        : "+f"(c[0]), "+f"(c[1]), "+f"(c[2]), "+f"(c[3])
        : "r"(a0), "r"(a1), "r"(a2), "r"(a3), "r"(b0), "r"(b1));
}
__device__ __forceinline__ uint32_t packh2(float lo, float hi) {
    __half2 h = __floats2half2_rn(lo, hi);
    return *(uint32_t*)&h;
}

// ===================== scratch =====================
__device__ __align__(16) __half g_x16[2 * 256 * 4096];     // [b][c][n]
__device__ __align__(16) __half g_w16[768 * 256];          // [o][c]
__device__ __align__(16) __half g_q16[2 * 4 * 4096 * 64];  // [bh][n][d], pre-scaled x0.125
__device__ __align__(16) __half g_k16[2 * 4 * 4096 * 64];  // [bh][n][d]
__device__ __align__(16) __half g_v16[2 * 4 * 64 * 4096];  // [bh][dv][m]
__device__ float g_qh[8 * 4096 * 128];                     // [bh][n][r]
__device__ float g_qw[8 * 4096 * 128];                     // [bh][n][r]

// ---------------------------------------------------------------------------
// Kernel 0: fp32 -> fp16 conversion for x and w
// ---------------------------------------------------------------------------
#define X_F4 524288
#define W_F4 49152
__global__ void __launch_bounds__(256) cvt_kernel(const float* __restrict__ x,
                                                  const float* __restrict__ w) {
    const int idx = blockIdx.x * 256 + threadIdx.x;
    if (idx < X_F4) {
        float4 v = ((const float4*)x)[idx];
        __half2* o = (__half2*)g_x16 + idx * 2;
        o[0] = __floats2half2_rn(v.x, v.y);
        o[1] = __floats2half2_rn(v.z, v.w);
    } else if (idx < X_F4 + W_F4) {
        float4 v = ((const float4*)w)[idx - X_F4];
        __half2* o = (__half2*)g_w16 + (idx - X_F4) * 2;
        o[0] = __floats2half2_rn(v.x, v.y);
        o[1] = __floats2half2_rn(v.z, v.w);
    }
}

// ---------------------------------------------------------------------------
// Kernel 1: QKV projection, fp16 tensor-core GEMM (unchanged from R6).
// ---------------------------------------------------------------------------
__global__ void __launch_bounds__(256, 1) qkv_mma_kernel() {
    extern __shared__ __align__(128) char smem[];
    const uint32_t sb = smem_to_u32(smem);
    const int t = threadIdx.x;
    const int w = t >> 5, lane = t & 31;
    const int gid = lane >> 2, tig = lane & 3;
    const int wo = w >> 1, wn = w & 1;
    const int n0 = blockIdx.x * 128;
    const int ot = blockIdx.y;
    const int b = blockIdx.z;

    const __half* wg = g_w16 + (size_t)ot * 128 * 256;
    const __half* xg = g_x16 + (size_t)b * 256 * 4096 + n0;

    auto load_stage = [&](int kc, int s) {
        const uint32_t As = sb + s * 32768;
        const uint32_t Bs = As + 16384;
        for (int idx = t; idx < 1024; idx += 256) {
            int row = idx >> 3, ch = idx & 7;
            cp16(As + row * 128 + ((ch ^ (row & 7)) * 16),
                 wg + (size_t)row * 256 + kc * 64 + ch * 8);
        }
        for (int idx = t; idx < 1024; idx += 256) {
            int row = idx >> 4, ch = idx & 15;
            cp16(Bs + row * 256 + ((ch ^ (row & 7)) * 16),
                 xg + (size_t)(kc * 64 + row) * 4096 + ch * 8);
        }
        CP_COMMIT();
    };

    float C[2][8][4];
#pragma unroll
    for (int mt = 0; mt < 2; mt++)
#pragma unroll
        for (int ng = 0; ng < 8; ng++)
#pragma unroll
            for (int e = 0; e < 4; e++) C[mt][ng][e] = 0.f;

    load_stage(0, 0);

    const int a_rlane = ((lane >> 3) & 1) * 8 + (lane & 7);
    const uint32_t a_x = (lane & 7) * 16;
    const int b_row = lane & 15;
    const int b_cg = lane >> 4;

    for (int kc = 0; kc < 4; kc++) {
        if (kc + 1 < 4) {
            load_stage(kc + 1, (kc + 1) & 1);
            cp_wait<1>();
        } else {
            cp_wait<0>();
        }
        __syncthreads();
        const uint32_t As = sb + (kc & 1) * 32768;
        const uint32_t Bs = As + 16384;

#pragma unroll
        for (int ks = 0; ks < 4; ks++) {
            uint32_t af[2][4];
#pragma unroll
            for (int mt = 0; mt < 2; mt++) {
                int arow = wo * 32 + mt * 16 + a_rlane;
                ldm_x4(af[mt][0], af[mt][1], af[mt][2], af[mt][3],
                       As + arow * 128 + (((uint32_t)((ks * 2 + (lane >> 4)) * 16)) ^ a_x));
            }
#pragma unroll
            for (int ng2 = 0; ng2 < 4; ng2++) {
                uint32_t b0, b1, b2, b3;
                int brow = ks * 16 + b_row;
                int bch = wn * 8 + ng2 * 2 + b_cg;
                ldm_x4t(b0, b1, b2, b3,
                        Bs + brow * 256 + ((bch ^ (brow & 7)) * 16));
#pragma unroll
                for (int mt = 0; mt < 2; mt++) {
                    mma_f16(C[mt][2 * ng2], af[mt][0], af[mt][1], af[mt][2], af[mt][3], b0, b1);
                    mma_f16(C[mt][2 * ng2 + 1], af[mt][0], af[mt][1], af[mt][2], af[mt][3], b2, b3);
                }
            }
        }
        __syncthreads();
    }

    const float sc = (ot < 2) ? SCALE_F : 1.0f;
    __half* Cs = (__half*)smem;
    if (ot < 4) {
#pragma unroll
        for (int mt = 0; mt < 2; mt++) {
            const int r_lo = wo * 32 + mt * 16 + gid, r_hi = r_lo + 8;
#pragma unroll
            for (int ng = 0; ng < 8; ng++) {
                const int c = wn * 64 + ng * 8 + 2 * tig;
                Cs[(c + 0) * 136 + r_lo] = __float2half_rn(C[mt][ng][0] * sc);
                Cs[(c + 1) * 136 + r_lo] = __float2half_rn(C[mt][ng][1] * sc);
                Cs[(c + 0) * 136 + r_hi] = __float2half_rn(C[mt][ng][2] * sc);
                Cs[(c + 1) * 136 + r_hi] = __float2half_rn(C[mt][ng][3] * sc);
            }
        }
        __syncthreads();
        __half* dst = (ot < 2) ? g_q16 : g_k16;
        const int otq = (ot < 2) ? ot : (ot - 2);
        for (int idx = t; idx < 2048; idx += 256) {
            int n = idx >> 4, hs = (idx >> 3) & 1, ch = idx & 7;
            int bh = b * 4 + otq * 2 + hs;
            *(uint4*)(dst + ((size_t)bh * 4096 + n0 + n) * 64 + ch * 8) =
                *(const uint4*)(Cs + n * 136 + hs * 64 + ch * 8);
        }
    } else {
#pragma unroll
        for (int mt = 0; mt < 2; mt++) {
            const int r_lo = wo * 32 + mt * 16 + gid, r_hi = r_lo + 8;
#pragma unroll
            for (int ng = 0; ng < 8; ng++) {
                const int c = wn * 64 + ng * 8 + 2 * tig;
                *(__half2*)(Cs + r_lo * 136 + c) = __floats2half2_rn(C[mt][ng][0], C[mt][ng][1]);
                *(__half2*)(Cs + r_hi * 136 + c) = __floats2half2_rn(C[mt][ng][2], C[mt][ng][3]);
            }
        }
        __syncthreads();
        const int otv = ot - 4;
        for (int idx = t; idx < 2048; idx += 256) {
            int lo = idx >> 4, ch = idx & 15;
            int bh = b * 4 + otv * 2 + (lo >> 6);
            int dv = lo & 63;
            *(uint4*)(g_v16 + ((size_t)bh * 64 + dv) * 4096 + n0 + ch * 8) =
                *(const uint4*)(Cs + lo * 136 + ch * 8);
        }
    }
}

// ---------------------------------------------------------------------------
// Kernel 2: rel-pos logits, fp16 mma (unchanged from R6).
// ---------------------------------------------------------------------------
__global__ void __launch_bounds__(256) rel_mma_kernel(const float* __restrict__ hrel,
                                                      const float* __restrict__ wrel) {
    __shared__ __align__(128) char smem_r[32768];
    const uint32_t sb = smem_to_u32(smem_r);
    const uint32_t Qs = sb;
    const uint32_t Rs = sb + 16384;
    const int t = threadIdx.x;
    const int w = t >> 5, lane = t & 31;
    const int gid = lane >> 2, tig = lane & 3;
    const int bh = blockIdx.y;
    const int n0 = blockIdx.x * 128;
    const float* rel = blockIdx.z ? wrel : hrel;
    float* outb = blockIdx.z ? g_qw : g_qh;

    for (int idx = t; idx < 1024; idx += 256) {
        int row = idx >> 3, ch = idx & 7;
        cp16(Qs + row * 128 + ((ch ^ (row & 7)) * 16),
             g_q16 + ((size_t)bh * 4096 + n0 + row) * 64 + ch * 8);
    }
    CP_COMMIT();
    for (int idx = t; idx < 1024; idx += 256) {
        int r = idx >> 3, ch = idx & 7;
        __half2 h[4];
        if (r < 127) {
            float4 v0 = *(const float4*)(rel + r * 64 + ch * 8);
            float4 v1 = *(const float4*)(rel + r * 64 + ch * 8 + 4);
            h[0] = __floats2half2_rn(v0.x * 8.f, v0.y * 8.f);
            h[1] = __floats2half2_rn(v0.z * 8.f, v0.w * 8.f);
            h[2] = __floats2half2_rn(v1.x * 8.f, v1.y * 8.f);
            h[3] = __floats2half2_rn(v1.z * 8.f, v1.w * 8.f);
        } else {
            h[0] = h[1] = h[2] = h[3] = __floats2half2_rn(0.f, 0.f);
        }
        *(uint4*)((char*)smem_r + 16384 + r * 128 + ((ch ^ (r & 7)) * 16)) = *(uint4*)h;
    }
    cp_wait<0>();
    __syncthreads();

    const int r0 = w * 16;
    uint32_t qf[4][4];
    {
        const int qrow = r0 + ((lane >> 3) & 1) * 8 + (lane & 7);
        const uint32_t qx = (lane & 7) * 16;
#pragma unroll
        for (int kt = 0; kt < 4; kt++)
            ldm_x4(qf[kt][0], qf[kt][1], qf[kt][2], qf[kt][3],
                   Qs + qrow * 128 + (((uint32_t)((kt * 2 + (lane >> 4)) * 16)) ^ qx));
    }

    const int kv_row = ((lane >> 4) & 1) * 8 + (lane & 7);
    const int kv_csel = (lane >> 3) & 1;
    const uint32_t kv_x = (lane & 7) * 16;

    float S[16][4];
#pragma unroll
    for (int nt = 0; nt < 16; nt++)
#pragma unroll
        for (int e = 0; e < 4; e++) S[nt][e] = 0.f;

#pragma unroll
    for (int kt = 0; kt < 4; kt++) {
#pragma unroll
        for (int ntp = 0; ntp < 8; ntp++) {
            uint32_t b0, b1, b2, b3;
            ldm_x4(b0, b1, b2, b3,
                   Rs + (uint32_t)(ntp * 16 + kv_row) * 128 +
                       (((uint32_t)((kt * 2 + kv_csel) * 16)) ^ kv_x));
            mma_f16(S[2 * ntp], qf[kt][0], qf[kt][1], qf[kt][2], qf[kt][3], b0, b1);
            mma_f16(S[2 * ntp + 1], qf[kt][0], qf[kt][1], qf[kt][2], qf[kt][3], b2, b3);
        }
    }

    const int i_lo = r0 + gid, i_hi = i_lo + 8;
#pragma unroll
    for (int nt = 0; nt < 16; nt++) {
        const int c = nt * 8 + 2 * tig;
        *(float2*)(outb + ((size_t)bh * 4096 + n0 + i_lo) * 128 + c) =
            make_float2(S[nt][0], S[nt][1]);
        *(float2*)(outb + ((size_t)bh * 4096 + n0 + i_hi) * 128 + c) =
            make_float2(S[nt][2], S[nt][3]);
    }
}

// ---------------------------------------------------------------------------
// Kernel 3: fp16 flash attention, 2 CTAs/SM, split-Bc (2 x 32-key sub-steps).
// ---------------------------------------------------------------------------
#define QW_STRIDE 66
#define QW_OFF 49152
#define FL_SMEM (49152 + 128 * QW_STRIDE * 4)  // 82944 B

__global__ void __launch_bounds__(256, 2) flash_kernel(float* __restrict__ out) {
    extern __shared__ __align__(128) char smem[];
    const uint32_t sb = smem_to_u32(smem);
    const uint32_t Qs = sb;  // 16384
    const uint32_t Kbuf0 = sb + 16384, Kbuf1 = sb + 24576;
    const uint32_t Vbuf0 = sb + 32768, Vbuf1 = sb + 40960;
    float* Qw = (float*)(smem + QW_OFF);  // [i][c] stride 66

    const int t = threadIdx.x;
    const int w = t >> 5, lane = t & 31;
    const int gid = lane >> 2, tig = lane & 3;
    const int r0 = w * 16;
    const int bh = blockIdx.y, qb = blockIdx.x;
    const int n0q = qb * 128;
    const __half* qg = g_q16 + (size_t)bh * 4096 * 64;
    const __half* kg = g_k16 + (size_t)bh * 4096 * 64;
    const __half* vg = g_v16 + (size_t)bh * 64 * 4096;

    for (int c = t; c < 1024; c += 256) {
        int row = c >> 3, kc = c & 7;
        cp16(Qs + row * 128 + ((kc * 16) ^ ((row & 7) * 16)),
             qg + (size_t)(n0q + row) * 64 + kc * 8);
    }
    for (int c = t; c < 512; c += 256) {
        int row = c >> 3, kc = c & 7;
        uint32_t sw = (kc * 16) ^ ((row & 7) * 16);
        cp16(Kbuf0 + row * 128 + sw, kg + (size_t)row * 64 + kc * 8);
        cp16(Vbuf0 + row * 128 + sw, vg + (size_t)row * 4096 + kc * 8);
    }
    CP_COMMIT();

    // width-bias gather -> smem (each thread writes exactly its own 16 cells)
    const int i_lo = r0 + gid, i_hi = i_lo + 8;
    {
        const float* qwb = g_qw + ((size_t)bh * 4096 + n0q) * 128;
#pragma unroll
        for (int nt = 0; nt < 8; nt++) {
            int c = nt * 8 + 2 * tig;
            Qw[i_lo * QW_STRIDE + c + 0] = qwb[(size_t)i_lo * 128 + (c - (i_lo & 63) + 63)];
            Qw[i_lo * QW_STRIDE + c + 1] = qwb[(size_t)i_lo * 128 + (c + 1 - (i_lo & 63) + 63)];
            Qw[i_hi * QW_STRIDE + c + 0] = qwb[(size_t)i_hi * 128 + (c - (i_hi & 63) + 63)];
            Qw[i_hi * QW_STRIDE + c + 1] = qwb[(size_t)i_hi * 128 + (c + 1 - (i_hi & 63) + 63)];
        }
    }
    cp_wait<0>();
    __syncthreads();

    uint32_t qf[4][4];
    {
        const int qrow = r0 + ((lane >> 3) & 1) * 8 + (lane & 7);
        const uint32_t qx = (lane & 7) * 16;
        const uint32_t qbase = Qs + qrow * 128;
#pragma unroll
        for (int kt = 0; kt < 4; kt++)
            ldm_x4(qf[kt][0], qf[kt][1], qf[kt][2], qf[kt][3],
                   qbase + ((uint32_t)((kt * 2 + (lane >> 4)) * 16) ^ qx));
    }

    const float* pqh_lo =
        g_qh + ((size_t)bh * 4096 + n0q + i_lo) * 128 + 63 - (qb * 2 + (i_lo >> 6));
    const float* pqh_hi =
        g_qh + ((size_t)bh * 4096 + n0q + i_hi) * 128 + 63 - (qb * 2 + (i_hi >> 6));
    const float* qw_lo = Qw + i_lo * QW_STRIDE + 2 * tig;
    const float* qw_hi = Qw + i_hi * QW_STRIDE + 2 * tig;

    const int kv_row = ((lane >> 4) & 1) * 8 + (lane & 7);
    const int kv_csel = (lane >> 3) & 1;
    const uint32_t kv_x = (lane & 7) * 16;

    float m_lo = -3.0e38f, m_hi = -3.0e38f, l_lo = 0.f, l_hi = 0.f;
    float O[8][4];
#pragma unroll
    for (int nt = 0; nt < 8; nt++)
#pragma unroll
        for (int e = 0; e < 4; e++) O[nt][e] = 0.f;

    for (int j = 0; j < 64; j++) {
        __syncthreads();
        if (j + 1 < 64) {
            const uint32_t kb = (j & 1) ? Kbuf0 : Kbuf1;
            const uint32_t vb = (j & 1) ? Vbuf0 : Vbuf1;
            for (int c = t; c < 512; c += 256) {
                int row = c >> 3, kc = c & 7;
                uint32_t sw = (kc * 16) ^ ((row & 7) * 16);
                cp16(kb + row * 128 + sw,
                     kg + ((size_t)(j + 1) * 64 + row) * 64 + kc * 8);
                cp16(vb + row * 128 + sw,
                     vg + (size_t)row * 4096 + (j + 1) * 64 + kc * 8);
            }
            CP_COMMIT();
            cp_wait<1>();
        } else {
            cp_wait<0>();
        }
        __syncthreads();

        const float qh_lo = pqh_lo[j], qh_hi = pqh_hi[j];
        const uint32_t Kb = (j & 1) ? Kbuf1 : Kbuf0;
        const uint32_t Vb = (j & 1) ? Vbuf1 : Vbuf0;

        // ---- two 32-key sub-steps (halves of the 64-key tile)
#pragma unroll
        for (int jj = 0; jj < 2; jj++) {
            float S[4][4];
#pragma unroll
            for (int nt = 0; nt < 4; nt++)
#pragma unroll
                for (int e = 0; e < 4; e++) S[nt][e] = 0.f;

#pragma unroll
            for (int kt = 0; kt < 4; kt++) {
#pragma unroll
                for (int ntl = 0; ntl < 2; ntl++) {
                    uint32_t b0, b1, b2, b3;
                    uint32_t addr = Kb + (uint32_t)((jj * 2 + ntl) * 16 + kv_row) * 128 +
                                    ((uint32_t)((kt * 2 + kv_csel) * 16) ^ kv_x);
                    ldm_x4(b0, b1, b2, b3, addr);
                    mma_f16(S[2 * ntl], qf[kt][0], qf[kt][1], qf[kt][2], qf[kt][3], b0, b1);
                    mma_f16(S[2 * ntl + 1], qf[kt][0], qf[kt][1], qf[kt][2], qf[kt][3], b2, b3);
                }
            }

            float mx_lo = -3.0e38f, mx_hi = -3.0e38f;
#pragma unroll
            for (int nt = 0; nt < 4; nt++) {
                const float2 b_lo = *(const float2*)(qw_lo + jj * 32 + nt * 8);
                const float2 b_hi = *(const float2*)(qw_hi + jj * 32 + nt * 8);
                S[nt][0] += qh_lo + b_lo.x;
                S[nt][1] += qh_lo + b_lo.y;
                S[nt][2] += qh_hi + b_hi.x;
                S[nt][3] += qh_hi + b_hi.y;
                mx_lo = fmaxf(mx_lo, fmaxf(S[nt][0], S[nt][1]));
                mx_hi = fmaxf(mx_hi, fmaxf(S[nt][2], S[nt][3]));
            }
            mx_lo = fmaxf(mx_lo, __shfl_xor_sync(0xffffffffu, mx_lo, 1));
            mx_lo = fmaxf(mx_lo, __shfl_xor_sync(0xffffffffu, mx_lo, 2));
            mx_hi = fmaxf(mx_hi, __shfl_xor_sync(0xffffffffu, mx_hi, 1));
            mx_hi = fmaxf(mx_hi, __shfl_xor_sync(0xffffffffu, mx_hi, 2));
            const float mnew_lo = fmaxf(m_lo, mx_lo);
            const float mnew_hi = fmaxf(m_hi, mx_hi);
            const float alpha_lo = __expf(m_lo - mnew_lo);
            const float alpha_hi = __expf(m_hi - mnew_hi);
            m_lo = mnew_lo; m_hi = mnew_hi;

            uint32_t ph[4][2];
            float sum_lo = 0.f, sum_hi = 0.f;
#pragma unroll
            for (int nt = 0; nt < 4; nt++) {
                float e0 = __expf(S[nt][0] - mnew_lo);
                float e1 = __expf(S[nt][1] - mnew_lo);
                float e2 = __expf(S[nt][2] - mnew_hi);
                float e3 = __expf(S[nt][3] - mnew_hi);
                sum_lo += e0 + e1;
                sum_hi += e2 + e3;
                ph[nt][0] = packh2(e0, e1);
                ph[nt][1] = packh2(e2, e3);
            }
            sum_lo += __shfl_xor_sync(0xffffffffu, sum_lo, 1);
            sum_lo += __shfl_xor_sync(0xffffffffu, sum_lo, 2);
            sum_hi += __shfl_xor_sync(0xffffffffu, sum_hi, 1);
            sum_hi += __shfl_xor_sync(0xffffffffu, sum_hi, 2);
            l_lo = l_lo * alpha_lo + sum_lo;
            l_hi = l_hi * alpha_hi + sum_hi;
#pragma unroll
            for (int nt = 0; nt < 8; nt++) {
                O[nt][0] *= alpha_lo; O[nt][1] *= alpha_lo;
                O[nt][2] *= alpha_hi; O[nt][3] *= alpha_hi;
            }

            // O += P_half @ V_half  (K dim = 32: kt chunks jj*2..jj*2+1)
#pragma unroll
            for (int ktl = 0; ktl < 2; ktl++) {
                const uint32_t pa0 = ph[2 * ktl][0], pa1 = ph[2 * ktl][1];
                const uint32_t pa2 = ph[2 * ktl + 1][0], pa3 = ph[2 * ktl + 1][1];
#pragma unroll
                for (int ntp = 0; ntp < 4; ntp++) {
                    uint32_t b0, b1, b2, b3;
                    uint32_t addr = Vb + (uint32_t)(ntp * 16 + kv_row) * 128 +
                                    ((uint32_t)(((jj * 2 + ktl) * 2 + kv_csel) * 16) ^ kv_x);
                    ldm_x4(b0, b1, b2, b3, addr);
                    mma_f16(O[2 * ntp], pa0, pa1, pa2, pa3, b0, b1);
                    mma_f16(O[2 * ntp + 1], pa0, pa1, pa2, pa3, b2, b3);
                }
            }
        }
    }

    __syncthreads();
    const float inv_lo = 1.0f / l_lo, inv_hi = 1.0f / l_hi;
    float* Os = (float*)smem;
#pragma unroll
    for (int nt = 0; nt < 8; nt++) {
        int dv = nt * 8 + 2 * tig;
        Os[(dv + 0) * 132 + i_lo] = O[nt][0] * inv_lo;
        Os[(dv + 1) * 132 + i_lo] = O[nt][1] * inv_lo;
        Os[(dv + 0) * 132 + i_hi] = O[nt][2] * inv_hi;
        Os[(dv + 1) * 132 + i_hi] = O[nt][3] * inv_hi;
    }
    __syncthreads();

    const int b = bh >> 2, head = bh & 3;
    float* outp = out + ((size_t)(b * 256 + head * 64)) * 4096 + n0q;
    for (int idx = t * 4; idx < 8192; idx += 1024) {
        int dv = idx >> 7, i = idx & 127;
        *(float4*)(outp + (size_t)dv * 4096 + i) = *(const float4*)(Os + dv * 132 + i);
    }
}

// ---------------------------------------------------------------------------
extern "C" void kernel_launch(void* const* d_in, const int* in_sizes, int n_in,
                              void* d_out, int out_size) {
    const float* x = (const float*)d_in[0];
    const float* w = (const float*)d_in[1];
    const float* hrel = (const float*)d_in[2];
    const float* wrel = (const float*)d_in[3];
    float* out = (float*)d_out;

    cvt_kernel<<<(X_F4 + W_F4 + 255) / 256, 256>>>(x, w);

    cudaFuncSetAttribute(qkv_mma_kernel, cudaFuncAttributeMaxDynamicSharedMemorySize,
                         65536);
    qkv_mma_kernel<<<dim3(32, 6, 2), 256, 65536>>>();

    rel_mma_kernel<<<dim3(32, 8, 2), 256>>>(hrel, wrel);

    cudaFuncSetAttribute(flash_kernel, cudaFuncAttributeMaxDynamicSharedMemorySize,
                         FL_SMEM);
    flash_kernel<<<dim3(32, 8), 256, FL_SMEM>>>(out);
}

// round 9
// speedup vs baseline: 1.4482x; 1.3329x over previous
#include <cuda_runtime.h>
#include <cuda_fp16.h>
#include <cstdint>
#include <cstddef>

#define SCALE_Q 0.18033688011112042f  // 0.125 * log2(e)
#define EXP_C 12.0f

__device__ __forceinline__ uint32_t smem_to_u32(const void* p) {
    uint32_t a;
    asm("{ .reg .u64 t; cvta.to.shared.u64 t, %1; cvt.u32.u64 %0, t; }" : "=r"(a) : "l"(p));
    return a;
}
__device__ __forceinline__ void cp16(uint32_t dst, const void* src) {
    asm volatile("cp.async.cg.shared.global [%0], [%1], 16;" :: "r"(dst), "l"(src) : "memory");
}
#define CP_COMMIT() asm volatile("cp.async.commit_group;" ::: "memory")
template <int N>
__device__ __forceinline__ void cp_wait() {
    asm volatile("cp.async.wait_group %0;" :: "n"(N) : "memory");
}
__device__ __forceinline__ void ldm_x4(uint32_t& r0, uint32_t& r1, uint32_t& r2,
                                       uint32_t& r3, uint32_t addr) {
    asm volatile("ldmatrix.sync.aligned.m8n8.x4.shared.b16 {%0,%1,%2,%3}, [%4];"
                 : "=r"(r0), "=r"(r1), "=r"(r2), "=r"(r3) : "r"(addr));
}
__device__ __forceinline__ void ldm_x4t(uint32_t& r0, uint32_t& r1, uint32_t& r2,
                                        uint32_t& r3, uint32_t addr) {
    asm volatile("ldmatrix.sync.aligned.m8n8.x4.trans.shared.b16 {%0,%1,%2,%3}, [%4];"
                 : "=r"(r0), "=r"(r1), "=r"(r2), "=r"(r3) : "r"(addr));
}
__device__ __forceinline__ void mma_f16(float c[4], uint32_t a0, uint32_t a1,
                                        uint32_t a2, uint32_t a3, uint32_t b0,
                                        uint32_t b1) {
    asm volatile(
        "mma.sync.aligned.m16n8k16.row.col.f32.f16.f16.f32 "
        "{%0,%1,%2,%3},{%4,%5,%6,%7},{%8,%9},{%0,%1,%2,%3};\n"
        : "+f"(c[0]), "+f"(c[1]), "+f"(c[2]), "+f"(c[3])
        : "r"(a0), "r"(a1), "r"(a2), "r"(a3), "r"(b0), "r"(b1));
}
__device__ __forceinline__ float ex2f(float x) {
    float r;
    asm("ex2.approx.ftz.f32 %0, %1;" : "=f"(r) : "f"(x));
    return r;
}
__device__ __forceinline__ uint32_t packh2(float lo, float hi) {
    __half2 h = __floats2half2_rn(lo, hi);
    return *(uint32_t*)&h;
}

// ===================== scratch =====================
__device__ __align__(16) __half g_x16[2 * 256 * 4096];     // [b][c][n]
__device__ __align__(16) __half g_w16[768 * 256];          // [o][c]
__device__ __align__(16) __half g_q16[2 * 4 * 4096 * 64];  // [bh][n][d], x 0.125*log2e
__device__ __align__(16) __half g_k16[2 * 4 * 4096 * 64];  // [bh][n][d]
__device__ __align__(16) __half g_v16[2 * 4 * 64 * 4096];  // [bh][dv][m]
__device__ float g_qh[8 * 4096 * 128];                     // [bh][n][r]  (log2 domain)
__device__ float g_qw[8 * 4096 * 128];                     // [bh][n][r]  (log2 domain)

// ---------------------------------------------------------------------------
// Kernel 0: fp32 -> fp16 conversion for x and w
// ---------------------------------------------------------------------------
#define X_F4 524288
#define W_F4 49152
__global__ void __launch_bounds__(256) cvt_kernel(const float* __restrict__ x,
                                                  const float* __restrict__ w) {
    const int idx = blockIdx.x * 256 + threadIdx.x;
    if (idx < X_F4) {
        float4 v = ((const float4*)x)[idx];
        __half2* o = (__half2*)g_x16 + idx * 2;
        o[0] = __floats2half2_rn(v.x, v.y);
        o[1] = __floats2half2_rn(v.z, v.w);
    } else if (idx < X_F4 + W_F4) {
        float4 v = ((const float4*)w)[idx - X_F4];
        __half2* o = (__half2*)g_w16 + (idx - X_F4) * 2;
        o[0] = __floats2half2_rn(v.x, v.y);
        o[1] = __floats2half2_rn(v.z, v.w);
    }
}

// ---------------------------------------------------------------------------
// Kernel 1: QKV projection, fp16 tensor-core GEMM. Q scaled by 0.125*log2e.
// ---------------------------------------------------------------------------
__global__ void __launch_bounds__(256, 1) qkv_mma_kernel() {
    extern __shared__ __align__(128) char smem[];
    const uint32_t sb = smem_to_u32(smem);
    const int t = threadIdx.x;
    const int w = t >> 5, lane = t & 31;
    const int gid = lane >> 2, tig = lane & 3;
    const int wo = w >> 1, wn = w & 1;
    const int n0 = blockIdx.x * 128;
    const int ot = blockIdx.y;
    const int b = blockIdx.z;

    const __half* wg = g_w16 + (size_t)ot * 128 * 256;
    const __half* xg = g_x16 + (size_t)b * 256 * 4096 + n0;

    auto load_stage = [&](int kc, int s) {
        const uint32_t As = sb + s * 32768;
        const uint32_t Bs = As + 16384;
        for (int idx = t; idx < 1024; idx += 256) {
            int row = idx >> 3, ch = idx & 7;
            cp16(As + row * 128 + ((ch ^ (row & 7)) * 16),
                 wg + (size_t)row * 256 + kc * 64 + ch * 8);
        }
        for (int idx = t; idx < 1024; idx += 256) {
            int row = idx >> 4, ch = idx & 15;
            cp16(Bs + row * 256 + ((ch ^ (row & 7)) * 16),
                 xg + (size_t)(kc * 64 + row) * 4096 + ch * 8);
        }
        CP_COMMIT();
    };

    float C[2][8][4];
#pragma unroll
    for (int mt = 0; mt < 2; mt++)
#pragma unroll
        for (int ng = 0; ng < 8; ng++)
#pragma unroll
            for (int e = 0; e < 4; e++) C[mt][ng][e] = 0.f;

    load_stage(0, 0);

    const int a_rlane = ((lane >> 3) & 1) * 8 + (lane & 7);
    const uint32_t a_x = (lane & 7) * 16;
    const int b_row = lane & 15;
    const int b_cg = lane >> 4;

    for (int kc = 0; kc < 4; kc++) {
        if (kc + 1 < 4) {
            load_stage(kc + 1, (kc + 1) & 1);
            cp_wait<1>();
        } else {
            cp_wait<0>();
        }
        __syncthreads();
        const uint32_t As = sb + (kc & 1) * 32768;
        const uint32_t Bs = As + 16384;

#pragma unroll
        for (int ks = 0; ks < 4; ks++) {
            uint32_t af[2][4];
#pragma unroll
            for (int mt = 0; mt < 2; mt++) {
                int arow = wo * 32 + mt * 16 + a_rlane;
                ldm_x4(af[mt][0], af[mt][1], af[mt][2], af[mt][3],
                       As + arow * 128 + (((uint32_t)((ks * 2 + (lane >> 4)) * 16)) ^ a_x));
            }
#pragma unroll
            for (int ng2 = 0; ng2 < 4; ng2++) {
                uint32_t b0, b1, b2, b3;
                int brow = ks * 16 + b_row;
                int bch = wn * 8 + ng2 * 2 + b_cg;
                ldm_x4t(b0, b1, b2, b3,
                        Bs + brow * 256 + ((bch ^ (brow & 7)) * 16));
#pragma unroll
                for (int mt = 0; mt < 2; mt++) {
                    mma_f16(C[mt][2 * ng2], af[mt][0], af[mt][1], af[mt][2], af[mt][3], b0, b1);
                    mma_f16(C[mt][2 * ng2 + 1], af[mt][0], af[mt][1], af[mt][2], af[mt][3], b2, b3);
                }
            }
        }
        __syncthreads();
    }

    const float sc = (ot < 2) ? SCALE_Q : 1.0f;
    __half* Cs = (__half*)smem;
    if (ot < 4) {
#pragma unroll
        for (int mt = 0; mt < 2; mt++) {
            const int r_lo = wo * 32 + mt * 16 + gid, r_hi = r_lo + 8;
#pragma unroll
            for (int ng = 0; ng < 8; ng++) {
                const int c = wn * 64 + ng * 8 + 2 * tig;
                Cs[(c + 0) * 136 + r_lo] = __float2half_rn(C[mt][ng][0] * sc);
                Cs[(c + 1) * 136 + r_lo] = __float2half_rn(C[mt][ng][1] * sc);
                Cs[(c + 0) * 136 + r_hi] = __float2half_rn(C[mt][ng][2] * sc);
                Cs[(c + 1) * 136 + r_hi] = __float2half_rn(C[mt][ng][3] * sc);
            }
        }
        __syncthreads();
        __half* dst = (ot < 2) ? g_q16 : g_k16;
        const int otq = (ot < 2) ? ot : (ot - 2);
        for (int idx = t; idx < 2048; idx += 256) {
            int n = idx >> 4, hs = (idx >> 3) & 1, ch = idx & 7;
            int bh = b * 4 + otq * 2 + hs;
            *(uint4*)(dst + ((size_t)bh * 4096 + n0 + n) * 64 + ch * 8) =
                *(const uint4*)(Cs + n * 136 + hs * 64 + ch * 8);
        }
    } else {
#pragma unroll
        for (int mt = 0; mt < 2; mt++) {
            const int r_lo = wo * 32 + mt * 16 + gid, r_hi = r_lo + 8;
#pragma unroll
            for (int ng = 0; ng < 8; ng++) {
                const int c = wn * 64 + ng * 8 + 2 * tig;
                *(__half2*)(Cs + r_lo * 136 + c) = __floats2half2_rn(C[mt][ng][0], C[mt][ng][1]);
                *(__half2*)(Cs + r_hi * 136 + c) = __floats2half2_rn(C[mt][ng][2], C[mt][ng][3]);
            }
        }
        __syncthreads();
        const int otv = ot - 4;
        for (int idx = t; idx < 2048; idx += 256) {
            int lo = idx >> 4, ch = idx & 15;
            int bh = b * 4 + otv * 2 + (lo >> 6);
            int dv = lo & 63;
            *(uint4*)(g_v16 + ((size_t)bh * 64 + dv) * 4096 + n0 + ch * 8) =
                *(const uint4*)(Cs + lo * 136 + ch * 8);
        }
    }
}

// ---------------------------------------------------------------------------
// Kernel 2: rel-pos logits, fp16 mma. (x8 unscale -> outputs in log2 domain
// automatically because q16 carries 0.125*log2e.)
// ---------------------------------------------------------------------------
__global__ void __launch_bounds__(256) rel_mma_kernel(const float* __restrict__ hrel,
                                                      const float* __restrict__ wrel) {
    __shared__ __align__(128) char smem_r[32768];
    const uint32_t sb = smem_to_u32(smem_r);
    const uint32_t Qs = sb;
    const uint32_t Rs = sb + 16384;
    const int t = threadIdx.x;
    const int w = t >> 5, lane = t & 31;
    const int gid = lane >> 2, tig = lane & 3;
    const int bh = blockIdx.y;
    const int n0 = blockIdx.x * 128;
    const float* rel = blockIdx.z ? wrel : hrel;
    float* outb = blockIdx.z ? g_qw : g_qh;

    for (int idx = t; idx < 1024; idx += 256) {
        int row = idx >> 3, ch = idx & 7;
        cp16(Qs + row * 128 + ((ch ^ (row & 7)) * 16),
             g_q16 + ((size_t)bh * 4096 + n0 + row) * 64 + ch * 8);
    }
    CP_COMMIT();
    for (int idx = t; idx < 1024; idx += 256) {
        int r = idx >> 3, ch = idx & 7;
        __half2 h[4];
        if (r < 127) {
            float4 v0 = *(const float4*)(rel + r * 64 + ch * 8);
            float4 v1 = *(const float4*)(rel + r * 64 + ch * 8 + 4);
            h[0] = __floats2half2_rn(v0.x * 8.f, v0.y * 8.f);
            h[1] = __floats2half2_rn(v0.z * 8.f, v0.w * 8.f);
            h[2] = __floats2half2_rn(v1.x * 8.f, v1.y * 8.f);
            h[3] = __floats2half2_rn(v1.z * 8.f, v1.w * 8.f);
        } else {
            h[0] = h[1] = h[2] = h[3] = __floats2half2_rn(0.f, 0.f);
        }
        *(uint4*)((char*)smem_r + 16384 + r * 128 + ((ch ^ (r & 7)) * 16)) = *(uint4*)h;
    }
    cp_wait<0>();
    __syncthreads();

    const int r0 = w * 16;
    uint32_t qf[4][4];
    {
        const int qrow = r0 + ((lane >> 3) & 1) * 8 + (lane & 7);
        const uint32_t qx = (lane & 7) * 16;
#pragma unroll
        for (int kt = 0; kt < 4; kt++)
            ldm_x4(qf[kt][0], qf[kt][1], qf[kt][2], qf[kt][3],
                   Qs + qrow * 128 + (((uint32_t)((kt * 2 + (lane >> 4)) * 16)) ^ qx));
    }

    const int kv_row = ((lane >> 4) & 1) * 8 + (lane & 7);
    const int kv_csel = (lane >> 3) & 1;
    const uint32_t kv_x = (lane & 7) * 16;

    float S[16][4];
#pragma unroll
    for (int nt = 0; nt < 16; nt++)
#pragma unroll
        for (int e = 0; e < 4; e++) S[nt][e] = 0.f;

#pragma unroll
    for (int kt = 0; kt < 4; kt++) {
#pragma unroll
        for (int ntp = 0; ntp < 8; ntp++) {
            uint32_t b0, b1, b2, b3;
            ldm_x4(b0, b1, b2, b3,
                   Rs + (uint32_t)(ntp * 16 + kv_row) * 128 +
                       (((uint32_t)((kt * 2 + kv_csel) * 16)) ^ kv_x));
            mma_f16(S[2 * ntp], qf[kt][0], qf[kt][1], qf[kt][2], qf[kt][3], b0, b1);
            mma_f16(S[2 * ntp + 1], qf[kt][0], qf[kt][1], qf[kt][2], qf[kt][3], b2, b3);
        }
    }

    const int i_lo = r0 + gid, i_hi = i_lo + 8;
#pragma unroll
    for (int nt = 0; nt < 16; nt++) {
        const int c = nt * 8 + 2 * tig;
        *(float2*)(outb + ((size_t)bh * 4096 + n0 + i_lo) * 128 + c) =
            make_float2(S[nt][0], S[nt][1]);
        *(float2*)(outb + ((size_t)bh * 4096 + n0 + i_hi) * 128 + c) =
            make_float2(S[nt][2], S[nt][3]);
    }
}

// ---------------------------------------------------------------------------
// Kernel 3: fp16 flash attention (R6 structure, 1 CTA/SM) with max-free
// ex2-based softmax: P = ex2(S2 - 12), C cancels in O/l.
// ---------------------------------------------------------------------------
#define FL_SMEM 49152

__global__ void __launch_bounds__(256, 1) flash_kernel(float* __restrict__ out) {
    extern __shared__ __align__(128) char smem[];
    const uint32_t sb = smem_to_u32(smem);
    const uint32_t Qs = sb;  // 16384
    const uint32_t Kbuf0 = sb + 16384, Kbuf1 = sb + 24576;
    const uint32_t Vbuf0 = sb + 32768, Vbuf1 = sb + 40960;

    const int t = threadIdx.x;
    const int w = t >> 5, lane = t & 31;
    const int gid = lane >> 2, tig = lane & 3;
    const int r0 = w * 16;
    const int bh = blockIdx.y, qb = blockIdx.x;
    const int n0q = qb * 128;
    const __half* qg = g_q16 + (size_t)bh * 4096 * 64;
    const __half* kg = g_k16 + (size_t)bh * 4096 * 64;
    const __half* vg = g_v16 + (size_t)bh * 64 * 4096;

    for (int c = t; c < 1024; c += 256) {
        int row = c >> 3, kc = c & 7;
        cp16(Qs + row * 128 + ((kc * 16) ^ ((row & 7) * 16)),
             qg + (size_t)(n0q + row) * 64 + kc * 8);
    }
    for (int c = t; c < 512; c += 256) {
        int row = c >> 3, kc = c & 7;
        uint32_t sw = (kc * 16) ^ ((row & 7) * 16);
        cp16(Kbuf0 + row * 128 + sw, kg + (size_t)row * 64 + kc * 8);
        cp16(Vbuf0 + row * 128 + sw, vg + (size_t)row * 4096 + kc * 8);
    }
    CP_COMMIT();
    cp_wait<0>();
    __syncthreads();

    uint32_t qf[4][4];
    {
        const int qrow = r0 + ((lane >> 3) & 1) * 8 + (lane & 7);
        const uint32_t qx = (lane & 7) * 16;
        const uint32_t qbase = Qs + qrow * 128;
#pragma unroll
        for (int kt = 0; kt < 4; kt++)
            ldm_x4(qf[kt][0], qf[kt][1], qf[kt][2], qf[kt][3],
                   qbase + ((uint32_t)((kt * 2 + (lane >> 4)) * 16) ^ qx));
    }

    const int i_lo = r0 + gid, i_hi = i_lo + 8;
    float qwv[8][4];
    {
        const float* qwb = g_qw + ((size_t)bh * 4096 + n0q) * 128;
#pragma unroll
        for (int nt = 0; nt < 8; nt++) {
            int c = nt * 8 + 2 * tig;
            qwv[nt][0] = qwb[(size_t)i_lo * 128 + (c - (i_lo & 63) + 63)];
            qwv[nt][1] = qwb[(size_t)i_lo * 128 + (c + 1 - (i_lo & 63) + 63)];
            qwv[nt][2] = qwb[(size_t)i_hi * 128 + (c - (i_hi & 63) + 63)];
            qwv[nt][3] = qwb[(size_t)i_hi * 128 + (c + 1 - (i_hi & 63) + 63)];
        }
    }
    const float* pqh_lo =
        g_qh + ((size_t)bh * 4096 + n0q + i_lo) * 128 + 63 - (qb * 2 + (i_lo >> 6));
    const float* pqh_hi =
        g_qh + ((size_t)bh * 4096 + n0q + i_hi) * 128 + 63 - (qb * 2 + (i_hi >> 6));

    const int kv_row = ((lane >> 4) & 1) * 8 + (lane & 7);
    const int kv_csel = (lane >> 3) & 1;
    const uint32_t kv_x = (lane & 7) * 16;

    float l_lo = 0.f, l_hi = 0.f;
    float O[8][4];
#pragma unroll
    for (int nt = 0; nt < 8; nt++)
#pragma unroll
        for (int e = 0; e < 4; e++) O[nt][e] = 0.f;

    for (int j = 0; j < 64; j++) {
        __syncthreads();
        if (j + 1 < 64) {
            const uint32_t kb = (j & 1) ? Kbuf0 : Kbuf1;
            const uint32_t vb = (j & 1) ? Vbuf0 : Vbuf1;
            for (int c = t; c < 512; c += 256) {
                int row = c >> 3, kc = c & 7;
                uint32_t sw = (kc * 16) ^ ((row & 7) * 16);
                cp16(kb + row * 128 + sw,
                     kg + ((size_t)(j + 1) * 64 + row) * 64 + kc * 8);
                cp16(vb + row * 128 + sw,
                     vg + (size_t)row * 4096 + (j + 1) * 64 + kc * 8);
            }
            CP_COMMIT();
            cp_wait<1>();
        } else {
            cp_wait<0>();
        }
        __syncthreads();

        const float qhc_lo = pqh_lo[j] - EXP_C;
        const float qhc_hi = pqh_hi[j] - EXP_C;
        const uint32_t Kb = (j & 1) ? Kbuf1 : Kbuf0;
        const uint32_t Vb = (j & 1) ? Vbuf1 : Vbuf0;

        float S[8][4];
#pragma unroll
        for (int nt = 0; nt < 8; nt++)
#pragma unroll
            for (int e = 0; e < 4; e++) S[nt][e] = 0.f;

#pragma unroll
        for (int kt = 0; kt < 4; kt++) {
#pragma unroll
            for (int ntp = 0; ntp < 4; ntp++) {
                uint32_t b0, b1, b2, b3;
                uint32_t addr = Kb + (uint32_t)(ntp * 16 + kv_row) * 128 +
                                ((uint32_t)((kt * 2 + kv_csel) * 16) ^ kv_x);
                ldm_x4(b0, b1, b2, b3, addr);
                mma_f16(S[2 * ntp], qf[kt][0], qf[kt][1], qf[kt][2], qf[kt][3], b0, b1);
                mma_f16(S[2 * ntp + 1], qf[kt][0], qf[kt][1], qf[kt][2], qf[kt][3], b2, b3);
            }
        }

        // ---- max-free softmax: P = ex2(S + qh + qw - C)
        uint32_t ph[8][2];
        float sum_lo = 0.f, sum_hi = 0.f;
#pragma unroll
        for (int nt = 0; nt < 8; nt++) {
            float e0 = ex2f(S[nt][0] + (qhc_lo + qwv[nt][0]));
            float e1 = ex2f(S[nt][1] + (qhc_lo + qwv[nt][1]));
            float e2 = ex2f(S[nt][2] + (qhc_hi + qwv[nt][2]));
            float e3 = ex2f(S[nt][3] + (qhc_hi + qwv[nt][3]));
            sum_lo += e0 + e1;
            sum_hi += e2 + e3;
            ph[nt][0] = packh2(e0, e1);
            ph[nt][1] = packh2(e2, e3);
        }
        l_lo += sum_lo;
        l_hi += sum_hi;

        // ---- O += P @ V
#pragma unroll
        for (int kt = 0; kt < 4; kt++) {
            const uint32_t pa0 = ph[2 * kt][0], pa1 = ph[2 * kt][1];
            const uint32_t pa2 = ph[2 * kt + 1][0], pa3 = ph[2 * kt + 1][1];
#pragma unroll
            for (int ntp = 0; ntp < 4; ntp++) {
                uint32_t b0, b1, b2, b3;
                uint32_t addr = Vb + (uint32_t)(ntp * 16 + kv_row) * 128 +
                                ((uint32_t)((kt * 2 + kv_csel) * 16) ^ kv_x);
                ldm_x4(b0, b1, b2, b3, addr);
                mma_f16(O[2 * ntp], pa0, pa1, pa2, pa3, b0, b1);
                mma_f16(O[2 * ntp + 1], pa0, pa1, pa2, pa3, b2, b3);
            }
        }
    }

    // ---- row sums across the quad (lanes tig 0..3 hold disjoint column sets)
    l_lo += __shfl_xor_sync(0xffffffffu, l_lo, 1);
    l_lo += __shfl_xor_sync(0xffffffffu, l_lo, 2);
    l_hi += __shfl_xor_sync(0xffffffffu, l_hi, 1);
    l_hi += __shfl_xor_sync(0xffffffffu, l_hi, 2);

    __syncthreads();
    const float inv_lo = 1.0f / l_lo, inv_hi = 1.0f / l_hi;
    float* Os = (float*)smem;
#pragma unroll
    for (int nt = 0; nt < 8; nt++) {
        int dv = nt * 8 + 2 * tig;
        Os[(dv + 0) * 132 + i_lo] = O[nt][0] * inv_lo;
        Os[(dv + 1) * 132 + i_lo] = O[nt][1] * inv_lo;
        Os[(dv + 0) * 132 + i_hi] = O[nt][2] * inv_hi;
        Os[(dv + 1) * 132 + i_hi] = O[nt][3] * inv_hi;
    }
    __syncthreads();

    const int b = bh >> 2, head = bh & 3;
    float* outp = out + ((size_t)(b * 256 + head * 64)) * 4096 + n0q;
    for (int idx = t * 4; idx < 8192; idx += 1024) {
        int dv = idx >> 7, i = idx & 127;
        *(float4*)(outp + (size_t)dv * 4096 + i) = *(const float4*)(Os + dv * 132 + i);
    }
}

// ---------------------------------------------------------------------------
extern "C" void kernel_launch(void* const* d_in, const int* in_sizes, int n_in,
                              void* d_out, int out_size) {
    const float* x = (const float*)d_in[0];
    const float* w = (const float*)d_in[1];
    const float* hrel = (const float*)d_in[2];
    const float* wrel = (const float*)d_in[3];
    float* out = (float*)d_out;

    cvt_kernel<<<(X_F4 + W_F4 + 255) / 256, 256>>>(x, w);

    cudaFuncSetAttribute(qkv_mma_kernel, cudaFuncAttributeMaxDynamicSharedMemorySize,
                         65536);
    qkv_mma_kernel<<<dim3(32, 6, 2), 256, 65536>>>();

    rel_mma_kernel<<<dim3(32, 8, 2), 256>>>(hrel, wrel);

    cudaFuncSetAttribute(flash_kernel, cudaFuncAttributeMaxDynamicSharedMemorySize,
                         FL_SMEM);
    flash_kernel<<<dim3(32, 8), 256, FL_SMEM>>>(out);
}